// round 11
// baseline (speedup 1.0000x reference)
#include <cuda_runtime.h>
#include <cuda_bf16.h>

#define NF    2048
#define NF4   (NF / 4)       // 512 float4 per row
#define GRID  888            // 148 SMs x 6 CTAs, exactly balanced
#define P     444            // row chunks == GRID/2
#define EPS   1e-6f

// Scratch (__device__ globals per allocation-free rule)
__device__ __align__(16) float g_ps[P * NF];   // partial sums   [p][c]
__device__ __align__(16) float g_pq[P * NF];   // partial sumsq  [p][c]
__device__ __align__(16) float g_mean[NF];
__device__ __align__(16) float g_istd[NF];

// Grid-barrier counters (zero-init; last CTA resets for graph replays)
__device__ unsigned g_bar1;
__device__ unsigned g_bar3;

__device__ __forceinline__ unsigned ld_acquire(unsigned* p) {
    unsigned v;
    asm volatile("ld.acquire.gpu.u32 %0, [%1];" : "=r"(v) : "l"(p) : "memory");
    return v;
}

__device__ __forceinline__ void st_release(unsigned* p, unsigned v) {
    asm volatile("st.release.gpu.u32 [%0], %1;" :: "l"(p), "r"(v) : "memory");
}

__device__ __forceinline__ void grid_barrier(unsigned* bar) {
    __syncthreads();
    __threadfence();
    if (threadIdx.x == 0) {
        atomicAdd(bar, 1u);
        while (ld_acquire(bar) < GRID) { __nanosleep(32); }
    }
    __syncthreads();
}

// ================= Kernel A: reduce + (barrier) + stats =================
__global__ void __launch_bounds__(256, 6)
reduce_stats_kernel(const float* __restrict__ x, int rows) {
    int bid  = blockIdx.x;
    int cb   = bid & 1;                 // column half: 0 or 1
    int p    = bid >> 1;                // row chunk 0..P-1
    int col4 = cb * 256 + threadIdx.x;  // 0..NF4-1
    int r0   = (int)(((long long)p * rows) / P);
    int r1   = (int)(((long long)(p + 1) * rows) / P);

    const float4* xp = reinterpret_cast<const float4*>(x);

    // ---------------- Phase 1: column reduce (MLP=4, fits 6 CTAs/SM) ------
    float sx = 0.f, sy = 0.f, sz = 0.f, sw = 0.f;
    float qx = 0.f, qy = 0.f, qz = 0.f, qw = 0.f;

    int r = r0;
    #pragma unroll 1
    for (; r + 4 <= r1; r += 4) {
        size_t base = (size_t)r * NF4 + col4;
        float4 v0 = xp[base];
        float4 v1 = xp[base + 1 * NF4];
        float4 v2 = xp[base + 2 * NF4];
        float4 v3 = xp[base + 3 * NF4];
        sx += v0.x; sy += v0.y; sz += v0.z; sw += v0.w;
        qx += v0.x*v0.x; qy += v0.y*v0.y; qz += v0.z*v0.z; qw += v0.w*v0.w;
        sx += v1.x; sy += v1.y; sz += v1.z; sw += v1.w;
        qx += v1.x*v1.x; qy += v1.y*v1.y; qz += v1.z*v1.z; qw += v1.w*v1.w;
        sx += v2.x; sy += v2.y; sz += v2.z; sw += v2.w;
        qx += v2.x*v2.x; qy += v2.y*v2.y; qz += v2.z*v2.z; qw += v2.w*v2.w;
        sx += v3.x; sy += v3.y; sz += v3.z; sw += v3.w;
        qx += v3.x*v3.x; qy += v3.y*v3.y; qz += v3.z*v3.z; qw += v3.w*v3.w;
    }
    #pragma unroll 1
    for (; r < r1; ++r) {
        float4 v = xp[(size_t)r * NF4 + col4];
        sx += v.x; sy += v.y; sz += v.z; sw += v.w;
        qx += v.x*v.x; qy += v.y*v.y; qz += v.z*v.z; qw += v.w*v.w;
    }

    {
        size_t o = (size_t)p * NF4 + col4;
        reinterpret_cast<float4*>(g_ps)[o] = make_float4(sx, sy, sz, sw);
        reinterpret_cast<float4*>(g_pq)[o] = make_float4(qx, qy, qz, qw);
    }

    grid_barrier(&g_bar1);

    // ------- Phase 2: stats. CTAs 0..511 each own col4 group == bid -------
    if (bid < NF4) {
        __shared__ float4 s_s[8];
        __shared__ float4 s_q[8];
        int t = threadIdx.x;
        float4 a = reinterpret_cast<const float4*>(g_ps)[(size_t)t * NF4 + bid];
        float4 b = reinterpret_cast<const float4*>(g_pq)[(size_t)t * NF4 + bid];
        if (t + 256 < P) {
            float4 a2 = reinterpret_cast<const float4*>(g_ps)[(size_t)(t + 256) * NF4 + bid];
            float4 b2 = reinterpret_cast<const float4*>(g_pq)[(size_t)(t + 256) * NF4 + bid];
            a.x += a2.x; a.y += a2.y; a.z += a2.z; a.w += a2.w;
            b.x += b2.x; b.y += b2.y; b.z += b2.z; b.w += b2.w;
        }
        #pragma unroll
        for (int off = 16; off > 0; off >>= 1) {
            a.x += __shfl_xor_sync(0xffffffffu, a.x, off);
            a.y += __shfl_xor_sync(0xffffffffu, a.y, off);
            a.z += __shfl_xor_sync(0xffffffffu, a.z, off);
            a.w += __shfl_xor_sync(0xffffffffu, a.w, off);
            b.x += __shfl_xor_sync(0xffffffffu, b.x, off);
            b.y += __shfl_xor_sync(0xffffffffu, b.y, off);
            b.z += __shfl_xor_sync(0xffffffffu, b.z, off);
            b.w += __shfl_xor_sync(0xffffffffu, b.w, off);
        }
        int warp = t >> 5, lane = t & 31;
        if (lane == 0) { s_s[warp] = a; s_q[warp] = b; }
        __syncthreads();
        if (warp == 0 && lane < 8) {
            a = s_s[lane]; b = s_q[lane];
            #pragma unroll
            for (int off = 4; off > 0; off >>= 1) {
                a.x += __shfl_xor_sync(0xffu, a.x, off);
                a.y += __shfl_xor_sync(0xffu, a.y, off);
                a.z += __shfl_xor_sync(0xffu, a.z, off);
                a.w += __shfl_xor_sync(0xffu, a.w, off);
                b.x += __shfl_xor_sync(0xffu, b.x, off);
                b.y += __shfl_xor_sync(0xffu, b.y, off);
                b.z += __shfl_xor_sync(0xffu, b.z, off);
                b.w += __shfl_xor_sync(0xffu, b.w, off);
            }
            if (lane == 0) {
                float n = (float)rows;
                float inv_n = 1.0f / n;
                float inv_n1 = 1.0f / (n - 1.0f);
                float4 m, is;
                m.x = a.x * inv_n; m.y = a.y * inv_n;
                m.z = a.z * inv_n; m.w = a.w * inv_n;
                is.x = rsqrtf((b.x - n * m.x * m.x) * inv_n1 + EPS);
                is.y = rsqrtf((b.y - n * m.y * m.y) * inv_n1 + EPS);
                is.z = rsqrtf((b.z - n * m.z * m.z) * inv_n1 + EPS);
                is.w = rsqrtf((b.w - n * m.w * m.w) * inv_n1 + EPS);
                reinterpret_cast<float4*>(g_mean)[bid] = m;
                reinterpret_cast<float4*>(g_istd)[bid] = is;
            }
        }
    }

    // ------- Reset barrier for next graph replay (all passed bar1) -------
    if (threadIdx.x == 0) {
        unsigned prev = atomicAdd(&g_bar3, 1u);
        if (prev == GRID - 1) {
            st_release(&g_bar1, 0u);
            st_release(&g_bar3, 0u);
        }
    }
}

// ================= Kernel B: normalize (multi-wave, rebalancing) =========
// __ldcs reads (x lines dead after read) + __stwt writes (no L2 allocation,
// keeps remaining x resident). Block covers 1024 consecutive float4 (2 rows).
__global__ void __launch_bounds__(256)
normalize_kernel(const float* __restrict__ x, float* __restrict__ out,
                 size_t n4) {
    size_t base = (size_t)blockIdx.x * 1024 + threadIdx.x;

    const float4* xp = reinterpret_cast<const float4*>(x);
    const float4* mp = reinterpret_cast<const float4*>(g_mean);
    const float4* sp = reinterpret_cast<const float4*>(g_istd);
    float4* op = reinterpret_cast<float4*>(out);

    size_t i0 = base, i1 = base + 256, i2 = base + 512, i3 = base + 768;
    if (i3 < n4) {
        float4 v0 = __ldcs(&xp[i0]);
        float4 v1 = __ldcs(&xp[i1]);
        float4 v2 = __ldcs(&xp[i2]);
        float4 v3 = __ldcs(&xp[i3]);
        int c0 = (int)(i0 & (NF4 - 1)), c1 = (int)(i1 & (NF4 - 1));
        int c2 = (int)(i2 & (NF4 - 1)), c3 = (int)(i3 & (NF4 - 1));
        float4 m0 = mp[c0], m1 = mp[c1], m2 = mp[c2], m3 = mp[c3];
        float4 s0 = sp[c0], s1 = sp[c1], s2 = sp[c2], s3 = sp[c3];
        float4 o0, o1, o2, o3;
        o0.x = (v0.x - m0.x) * s0.x; o0.y = (v0.y - m0.y) * s0.y;
        o0.z = (v0.z - m0.z) * s0.z; o0.w = (v0.w - m0.w) * s0.w;
        o1.x = (v1.x - m1.x) * s1.x; o1.y = (v1.y - m1.y) * s1.y;
        o1.z = (v1.z - m1.z) * s1.z; o1.w = (v1.w - m1.w) * s1.w;
        o2.x = (v2.x - m2.x) * s2.x; o2.y = (v2.y - m2.y) * s2.y;
        o2.z = (v2.z - m2.z) * s2.z; o2.w = (v2.w - m2.w) * s2.w;
        o3.x = (v3.x - m3.x) * s3.x; o3.y = (v3.y - m3.y) * s3.y;
        o3.z = (v3.z - m3.z) * s3.z; o3.w = (v3.w - m3.w) * s3.w;
        __stwt(&op[i0], o0);
        __stwt(&op[i1], o1);
        __stwt(&op[i2], o2);
        __stwt(&op[i3], o3);
    } else {
        #pragma unroll
        for (int k = 0; k < 4; k++) {
            size_t i = base + (size_t)k * 256;
            if (i < n4) {
                float4 v = __ldcs(&xp[i]);
                int c = (int)(i & (NF4 - 1));
                float4 m = mp[c], s = sp[c];
                float4 o;
                o.x = (v.x - m.x) * s.x; o.y = (v.y - m.y) * s.y;
                o.z = (v.z - m.z) * s.z; o.w = (v.w - m.w) * s.w;
                __stwt(&op[i], o);
            }
        }
    }
}

extern "C" void kernel_launch(void* const* d_in, const int* in_sizes, int n_in,
                              void* d_out, int out_size) {
    const float* x = (const float*)d_in[0];
    float* out = (float*)d_out;
    int rows = in_sizes[0] / NF;     // 8192

    // A: reduce + stats (persistent 888 CTAs, one internal grid barrier)
    reduce_stats_kernel<<<GRID, 256>>>(x, rows);

    // B: normalize (4096 CTAs, multi-wave)
    size_t n4 = (size_t)rows * NF4;
    int nblocks = (int)((n4 + 1023) / 1024);
    normalize_kernel<<<nblocks, 256>>>(x, out, n4);
}

// round 12
// speedup vs baseline: 1.1751x; 1.1751x over previous
#include <cuda_runtime.h>
#include <cuda_bf16.h>

#define NF    2048
#define NF4   (NF / 4)       // 512 float4 per row
#define GRID  592            // 148 SMs x 4 CTAs, exactly balanced
#define P     296            // row chunks == GRID/2
#define EPS   1e-6f

// Scratch (__device__ globals per allocation-free rule)
__device__ __align__(16) float g_ps[P * NF];   // partial sums   [p][c]
__device__ __align__(16) float g_pq[P * NF];   // partial sumsq  [p][c]
__device__ __align__(16) float g_mean[NF];
__device__ __align__(16) float g_istd[NF];

// Grid-barrier counters (zero-init; last CTA resets for graph replays)
__device__ unsigned g_bar1;
__device__ unsigned g_bar3;

__device__ __forceinline__ unsigned ld_acquire(unsigned* p) {
    unsigned v;
    asm volatile("ld.acquire.gpu.u32 %0, [%1];" : "=r"(v) : "l"(p) : "memory");
    return v;
}

__device__ __forceinline__ void st_release(unsigned* p, unsigned v) {
    asm volatile("st.release.gpu.u32 [%0], %1;" :: "l"(p), "r"(v) : "memory");
}

__device__ __forceinline__ void grid_barrier(unsigned* bar) {
    __syncthreads();
    __threadfence();
    if (threadIdx.x == 0) {
        atomicAdd(bar, 1u);
        while (ld_acquire(bar) < GRID) { __nanosleep(32); }
    }
    __syncthreads();
}

// ================= Kernel A: reduce (MLP=8) + barrier + stats =============
__global__ void __launch_bounds__(256, 4)
reduce_stats_kernel(const float* __restrict__ x, int rows) {
    int bid  = blockIdx.x;
    int cb   = bid & 1;                 // column half: 0 or 1
    int p    = bid >> 1;                // row chunk 0..P-1
    int col4 = cb * 256 + threadIdx.x;  // 0..NF4-1
    int r0   = (int)(((long long)p * rows) / P);
    int r1   = (int)(((long long)(p + 1) * rows) / P);

    const float4* xp = reinterpret_cast<const float4*>(x);

    float sx = 0.f, sy = 0.f, sz = 0.f, sw = 0.f;
    float qx = 0.f, qy = 0.f, qz = 0.f, qw = 0.f;

    int r = r0;
    #pragma unroll 1
    for (; r + 8 <= r1; r += 8) {
        size_t base = (size_t)r * NF4 + col4;
        float4 v0 = xp[base];
        float4 v1 = xp[base + 1 * NF4];
        float4 v2 = xp[base + 2 * NF4];
        float4 v3 = xp[base + 3 * NF4];
        float4 v4 = xp[base + 4 * NF4];
        float4 v5 = xp[base + 5 * NF4];
        float4 v6 = xp[base + 6 * NF4];
        float4 v7 = xp[base + 7 * NF4];
        sx += v0.x; sy += v0.y; sz += v0.z; sw += v0.w;
        qx += v0.x*v0.x; qy += v0.y*v0.y; qz += v0.z*v0.z; qw += v0.w*v0.w;
        sx += v1.x; sy += v1.y; sz += v1.z; sw += v1.w;
        qx += v1.x*v1.x; qy += v1.y*v1.y; qz += v1.z*v1.z; qw += v1.w*v1.w;
        sx += v2.x; sy += v2.y; sz += v2.z; sw += v2.w;
        qx += v2.x*v2.x; qy += v2.y*v2.y; qz += v2.z*v2.z; qw += v2.w*v2.w;
        sx += v3.x; sy += v3.y; sz += v3.z; sw += v3.w;
        qx += v3.x*v3.x; qy += v3.y*v3.y; qz += v3.z*v3.z; qw += v3.w*v3.w;
        sx += v4.x; sy += v4.y; sz += v4.z; sw += v4.w;
        qx += v4.x*v4.x; qy += v4.y*v4.y; qz += v4.z*v4.z; qw += v4.w*v4.w;
        sx += v5.x; sy += v5.y; sz += v5.z; sw += v5.w;
        qx += v5.x*v5.x; qy += v5.y*v5.y; qz += v5.z*v5.z; qw += v5.w*v5.w;
        sx += v6.x; sy += v6.y; sz += v6.z; sw += v6.w;
        qx += v6.x*v6.x; qy += v6.y*v6.y; qz += v6.z*v6.z; qw += v6.w*v6.w;
        sx += v7.x; sy += v7.y; sz += v7.z; sw += v7.w;
        qx += v7.x*v7.x; qy += v7.y*v7.y; qz += v7.z*v7.z; qw += v7.w*v7.w;
    }
    #pragma unroll 1
    for (; r < r1; ++r) {
        float4 v = xp[(size_t)r * NF4 + col4];
        sx += v.x; sy += v.y; sz += v.z; sw += v.w;
        qx += v.x*v.x; qy += v.y*v.y; qz += v.z*v.z; qw += v.w*v.w;
    }

    {
        size_t o = (size_t)p * NF4 + col4;
        reinterpret_cast<float4*>(g_ps)[o] = make_float4(sx, sy, sz, sw);
        reinterpret_cast<float4*>(g_pq)[o] = make_float4(qx, qy, qz, qw);
    }

    grid_barrier(&g_bar1);

    // ------- Phase 2: stats. CTAs 0..511 each own col4 group == bid -------
    if (bid < NF4) {
        __shared__ float4 s_s[8];
        __shared__ float4 s_q[8];
        int t = threadIdx.x;
        float4 a = reinterpret_cast<const float4*>(g_ps)[(size_t)t * NF4 + bid];
        float4 b = reinterpret_cast<const float4*>(g_pq)[(size_t)t * NF4 + bid];
        if (t + 256 < P) {
            float4 a2 = reinterpret_cast<const float4*>(g_ps)[(size_t)(t + 256) * NF4 + bid];
            float4 b2 = reinterpret_cast<const float4*>(g_pq)[(size_t)(t + 256) * NF4 + bid];
            a.x += a2.x; a.y += a2.y; a.z += a2.z; a.w += a2.w;
            b.x += b2.x; b.y += b2.y; b.z += b2.z; b.w += b2.w;
        }
        #pragma unroll
        for (int off = 16; off > 0; off >>= 1) {
            a.x += __shfl_xor_sync(0xffffffffu, a.x, off);
            a.y += __shfl_xor_sync(0xffffffffu, a.y, off);
            a.z += __shfl_xor_sync(0xffffffffu, a.z, off);
            a.w += __shfl_xor_sync(0xffffffffu, a.w, off);
            b.x += __shfl_xor_sync(0xffffffffu, b.x, off);
            b.y += __shfl_xor_sync(0xffffffffu, b.y, off);
            b.z += __shfl_xor_sync(0xffffffffu, b.z, off);
            b.w += __shfl_xor_sync(0xffffffffu, b.w, off);
        }
        int warp = t >> 5, lane = t & 31;
        if (lane == 0) { s_s[warp] = a; s_q[warp] = b; }
        __syncthreads();
        if (warp == 0 && lane < 8) {
            a = s_s[lane]; b = s_q[lane];
            #pragma unroll
            for (int off = 4; off > 0; off >>= 1) {
                a.x += __shfl_xor_sync(0xffu, a.x, off);
                a.y += __shfl_xor_sync(0xffu, a.y, off);
                a.z += __shfl_xor_sync(0xffu, a.z, off);
                a.w += __shfl_xor_sync(0xffu, a.w, off);
                b.x += __shfl_xor_sync(0xffu, b.x, off);
                b.y += __shfl_xor_sync(0xffu, b.y, off);
                b.z += __shfl_xor_sync(0xffu, b.z, off);
                b.w += __shfl_xor_sync(0xffu, b.w, off);
            }
            if (lane == 0) {
                float n = (float)rows;
                float inv_n = 1.0f / n;
                float inv_n1 = 1.0f / (n - 1.0f);
                float4 m, is;
                m.x = a.x * inv_n; m.y = a.y * inv_n;
                m.z = a.z * inv_n; m.w = a.w * inv_n;
                is.x = rsqrtf((b.x - n * m.x * m.x) * inv_n1 + EPS);
                is.y = rsqrtf((b.y - n * m.y * m.y) * inv_n1 + EPS);
                is.z = rsqrtf((b.z - n * m.z * m.z) * inv_n1 + EPS);
                is.w = rsqrtf((b.w - n * m.w * m.w) * inv_n1 + EPS);
                reinterpret_cast<float4*>(g_mean)[bid] = m;
                reinterpret_cast<float4*>(g_istd)[bid] = is;
            }
        }
    }

    // ------- Reset barrier for next graph replay (all passed bar1) -------
    if (threadIdx.x == 0) {
        unsigned prev = atomicAdd(&g_bar3, 1u);
        if (prev == GRID - 1) {
            st_release(&g_bar1, 0u);
            st_release(&g_bar3, 0u);
        }
    }
}

// ================= Kernel B: normalize (multi-wave) =====================
// Plain loads (want L2 hits on resident x) + __stcs stores (out lines go
// evict-first in L2 so they don't displace not-yet-read x).
__global__ void __launch_bounds__(256)
normalize_kernel(const float* __restrict__ x, float* __restrict__ out,
                 size_t n4) {
    size_t base = (size_t)blockIdx.x * 1024 + threadIdx.x;

    const float4* xp = reinterpret_cast<const float4*>(x);
    const float4* mp = reinterpret_cast<const float4*>(g_mean);
    const float4* sp = reinterpret_cast<const float4*>(g_istd);
    float4* op = reinterpret_cast<float4*>(out);

    size_t i0 = base, i1 = base + 256, i2 = base + 512, i3 = base + 768;
    if (i3 < n4) {
        float4 v0 = xp[i0], v1 = xp[i1], v2 = xp[i2], v3 = xp[i3];
        int c0 = (int)(i0 & (NF4 - 1)), c1 = (int)(i1 & (NF4 - 1));
        int c2 = (int)(i2 & (NF4 - 1)), c3 = (int)(i3 & (NF4 - 1));
        float4 m0 = mp[c0], m1 = mp[c1], m2 = mp[c2], m3 = mp[c3];
        float4 s0 = sp[c0], s1 = sp[c1], s2 = sp[c2], s3 = sp[c3];
        float4 o0, o1, o2, o3;
        o0.x = (v0.x - m0.x) * s0.x; o0.y = (v0.y - m0.y) * s0.y;
        o0.z = (v0.z - m0.z) * s0.z; o0.w = (v0.w - m0.w) * s0.w;
        o1.x = (v1.x - m1.x) * s1.x; o1.y = (v1.y - m1.y) * s1.y;
        o1.z = (v1.z - m1.z) * s1.z; o1.w = (v1.w - m1.w) * s1.w;
        o2.x = (v2.x - m2.x) * s2.x; o2.y = (v2.y - m2.y) * s2.y;
        o2.z = (v2.z - m2.z) * s2.z; o2.w = (v2.w - m2.w) * s2.w;
        o3.x = (v3.x - m3.x) * s3.x; o3.y = (v3.y - m3.y) * s3.y;
        o3.z = (v3.z - m3.z) * s3.z; o3.w = (v3.w - m3.w) * s3.w;
        __stcs(&op[i0], o0);
        __stcs(&op[i1], o1);
        __stcs(&op[i2], o2);
        __stcs(&op[i3], o3);
    } else {
        #pragma unroll
        for (int k = 0; k < 4; k++) {
            size_t i = base + (size_t)k * 256;
            if (i < n4) {
                float4 v = xp[i];
                int c = (int)(i & (NF4 - 1));
                float4 m = mp[c], s = sp[c];
                float4 o;
                o.x = (v.x - m.x) * s.x; o.y = (v.y - m.y) * s.y;
                o.z = (v.z - m.z) * s.z; o.w = (v.w - m.w) * s.w;
                __stcs(&op[i], o);
            }
        }
    }
}

extern "C" void kernel_launch(void* const* d_in, const int* in_sizes, int n_in,
                              void* d_out, int out_size) {
    const float* x = (const float*)d_in[0];
    float* out = (float*)d_out;
    int rows = in_sizes[0] / NF;     // 8192

    // A: reduce + stats (persistent 592 CTAs, one internal grid barrier)
    reduce_stats_kernel<<<GRID, 256>>>(x, rows);

    // B: normalize (4096 CTAs, multi-wave)
    size_t n4 = (size_t)rows * NF4;
    int nblocks = (int)((n4 + 1023) / 1024);
    normalize_kernel<<<nblocks, 256>>>(x, out, n4);
}